// round 3
// baseline (speedup 1.0000x reference)
#include <cuda_runtime.h>
#include <math.h>

#define BA 2048          // B*A
#define E  256
#define H  128
#define KF 12
#define NORM 0.08838834764831845f   // 1/sqrt(128)

// Scratch (static __device__ to satisfy no-alloc rule)
__device__ float g_qk [BA * H];          // vs0 @ (Wq @ Wk^T)
__device__ float g_wve[BA * H];          // sum_e score[e]*ve[e,:]
__device__ float g_veC[(size_t)BA * KF * H]; // gathered top-12 entity rows
__device__ float g_M  [H * H];           // Wq @ Wk^T
__device__ float g_P  [H * H];           // Wv @ W1[H:,:]

// ---------------------------------------------------------------------------
// Kernel 1: tiny 128x128 weight products. grid (128, 2), 128 threads.
//   m==0: M[r,c] = sum_d Wq[r,d] * Wk[c,d]
//   m==1: P[r,c] = sum_d Wv[r,d] * W1[(H+d), c]
// ---------------------------------------------------------------------------
__global__ void prep_MP(const float* __restrict__ Wq, const float* __restrict__ Wk,
                        const float* __restrict__ Wv, const float* __restrict__ W1)
{
    __shared__ float arow[H];
    int r = blockIdx.x;
    int c = threadIdx.x;
    int m = blockIdx.y;
    const float* A = (m == 0) ? Wq : Wv;
    arow[c] = A[r * H + c];
    __syncthreads();

    float acc = 0.0f;
    if (m == 0) {
        const float4* wk4 = (const float4*)(Wk + c * H);
        #pragma unroll 8
        for (int d4 = 0; d4 < H / 4; d4++) {
            float4 w = wk4[d4];
            acc += arow[4 * d4 + 0] * w.x + arow[4 * d4 + 1] * w.y
                 + arow[4 * d4 + 2] * w.z + arow[4 * d4 + 3] * w.w;
        }
        g_M[r * H + c] = acc;
    } else {
        #pragma unroll 8
        for (int d = 0; d < H; d++)
            acc = fmaf(arow[d], W1[(H + d) * H + c], acc);
        g_P[r * H + c] = acc;
    }
}

// ---------------------------------------------------------------------------
// Kernel 2: qk = vs0 @ M   ([2048,128] @ [128,128]). grid 128, 128 threads.
// ---------------------------------------------------------------------------
__global__ void qk_kernel(const float* __restrict__ vs)
{
    __shared__ float Ms[H * H];     // 64 KB
    __shared__ float xs[16 * H];
    int c  = threadIdx.x;
    int i0 = blockIdx.x * 16;
    for (int k = 0; k < H; k++) Ms[k * H + c] = g_M[k * H + c];
    for (int r = 0; r < 16; r++) xs[r * H + c] = vs[(i0 + r) * H + c];
    __syncthreads();
    for (int r = 0; r < 16; r++) {
        float acc = 0.0f;
        #pragma unroll 8
        for (int h = 0; h < H; h++)
            acc = fmaf(xs[r * H + h], Ms[h * H + c], acc);
        g_qk[(i0 + r) * H + c] = acc;
    }
}

// ---------------------------------------------------------------------------
// Kernel 3: MAIN. One CTA per (b,a). 256 threads.
//   pass1: stream ve tile (128 KB) from DRAM, compat = norm*ve.qk, mask dead
//   softmax (exact nan_to_num semantics)
//   pass2: wve = sum_e score*ve  (re-read, expected L2 hit)
//   top-12 (value desc, index asc -> matches jax.lax.top_k ties)
//   gather 12 rows into g_veC
// Static dummy smem (never touched at runtime) caps occupancy at 5 CTAs/SM:
// concurrent working set 148*5*128KB ~ 95 MB < 126 MB L2 -> pass-2 L2 hits.
// ---------------------------------------------------------------------------
#define DUMMY_F 10240    // 40 KB
__global__ void __launch_bounds__(256)
main_kernel(const float* __restrict__ ve, const int* __restrict__ dead)
{
    __shared__ float sscore[E];
    __shared__ float scopy [E];
    __shared__ float sred  [8];
    __shared__ float spart [H];
    __shared__ int   ssel  [KF];
    __shared__ float sdummy[DUMMY_F];   // occupancy limiter

    const int i   = blockIdx.x;
    const int tid = threadIdx.x;
    const int w   = tid >> 5;
    const int l   = tid & 31;

    if ((int)blockIdx.x == 0x7fffffff) {   // never true; keeps sdummy alive
        sdummy[tid] = (float)tid;
        __syncthreads();
        ((volatile float*)g_qk)[tid] = sdummy[255 - tid];
    }

    const float4* ve4 = (const float4*)(ve + (size_t)i * E * H);
    const float4  qk4 = ((const float4*)(g_qk + i * H))[l];
    const int*    dr  = dead + i * E;

    // ---- pass 1: compat ----
    #pragma unroll 2
    for (int eo = 0; eo < 32; eo += 4) {
        int e = w * 32 + eo;
        float4 r0 = ve4[(e + 0) * 32 + l];
        float4 r1 = ve4[(e + 1) * 32 + l];
        float4 r2 = ve4[(e + 2) * 32 + l];
        float4 r3 = ve4[(e + 3) * 32 + l];
        float s0 = r0.x * qk4.x + r0.y * qk4.y + r0.z * qk4.z + r0.w * qk4.w;
        float s1 = r1.x * qk4.x + r1.y * qk4.y + r1.z * qk4.z + r1.w * qk4.w;
        float s2 = r2.x * qk4.x + r2.y * qk4.y + r2.z * qk4.z + r2.w * qk4.w;
        float s3 = r3.x * qk4.x + r3.y * qk4.y + r3.z * qk4.z + r3.w * qk4.w;
        #pragma unroll
        for (int off = 16; off; off >>= 1) {
            s0 += __shfl_xor_sync(0xffffffffu, s0, off);
            s1 += __shfl_xor_sync(0xffffffffu, s1, off);
            s2 += __shfl_xor_sync(0xffffffffu, s2, off);
            s3 += __shfl_xor_sync(0xffffffffu, s3, off);
        }
        if (l < 4) {
            int ee = e + l;
            float sv = (l == 0) ? s0 : (l == 1) ? s1 : (l == 2) ? s2 : s3;
            sscore[ee] = dr[ee] ? -INFINITY : NORM * sv;
        }
    }
    __syncthreads();

    // ---- softmax over 256 (tid == entity) ----
    float x = sscore[tid];
    float mv = x;
    #pragma unroll
    for (int off = 16; off; off >>= 1)
        mv = fmaxf(mv, __shfl_xor_sync(0xffffffffu, mv, off));
    if (l == 0) sred[w] = mv;
    __syncthreads();
    if (tid == 0) {
        float m2 = sred[0];
        for (int j = 1; j < 8; j++) m2 = fmaxf(m2, sred[j]);
        sred[0] = m2;
    }
    __syncthreads();
    float gmax = sred[0];
    float p = (gmax == -INFINITY) ? 0.0f : __expf(x - gmax);
    __syncthreads();                     // everyone read sred[0] before reuse
    float sv = p;
    #pragma unroll
    for (int off = 16; off; off >>= 1)
        sv += __shfl_xor_sync(0xffffffffu, sv, off);
    if (l == 0) sred[w] = sv;
    __syncthreads();
    if (tid == 0) {
        float t2 = 0.0f;
        for (int j = 0; j < 8; j++) t2 += sred[j];
        sred[0] = t2;
    }
    __syncthreads();
    float tot = sred[0];
    float sc  = (tot > 0.0f) ? p * (1.0f / tot) : 0.0f;
    sscore[tid] = sc;
    scopy [tid] = sc;
    __syncthreads();

    // ---- pass 2: wve (re-read tile, expect L2 hits) ----
    const int h    = tid & 127;
    const int half = tid >> 7;
    const float* vb = ve + (size_t)i * E * H + (size_t)half * 128 * H;
    float acc = 0.0f;
    #pragma unroll 4
    for (int e2 = 0; e2 < 128; e2++)
        acc = fmaf(sscore[half * 128 + e2], vb[e2 * H + h], acc);
    if (half) spart[h] = acc;
    __syncthreads();
    if (!half) g_wve[i * H + h] = acc + spart[h];

    // ---- top-12 (warp 0) ----
    if (w == 0) {
        for (int k = 0; k < KF; k++) {
            float bv = -3.0f; int bi = 0;
            #pragma unroll
            for (int j = 0; j < 8; j++) {
                int e = j * 32 + l;
                float v = scopy[e];
                if (v > bv) { bv = v; bi = e; }   // ascending scan -> low idx wins ties
            }
            #pragma unroll
            for (int off = 16; off; off >>= 1) {
                float ov = __shfl_xor_sync(0xffffffffu, bv, off);
                int   oi = __shfl_xor_sync(0xffffffffu, bi, off);
                if (ov > bv || (ov == bv && oi < bi)) { bv = ov; bi = oi; }
            }
            if (l == 0) { ssel[k] = bi; scopy[bi] = -1.0f; }
            __syncwarp(0xffffffffu);
        }
    }
    __syncthreads();

    // ---- gather selected rows (8 warps cover 12 rows, strided) ----
    for (int k = w; k < KF; k += 8) {
        int e = ssel[k];
        ((float4*)g_veC)[((size_t)i * KF + k) * 32 + l] = ve4[e * 32 + l];
    }
}

// ---------------------------------------------------------------------------
// Kernel 4: v_M = relu(vs0@W1a + wve@P + b1)  -> out[BA*H ...]
// grid 128, 128 threads, 16 rows/block. Weights stay in L1 (reused 16x).
// ---------------------------------------------------------------------------
__global__ void vM_kernel(const float* __restrict__ vs, const float* __restrict__ W1,
                          const float* __restrict__ b1, float* __restrict__ out)
{
    __shared__ float sx[16 * H];
    __shared__ float sy[16 * H];
    int c  = threadIdx.x;
    int i0 = blockIdx.x * 16;
    for (int r = 0; r < 16; r++) {
        sx[r * H + c] = vs[(i0 + r) * H + c];
        sy[r * H + c] = g_wve[(i0 + r) * H + c];
    }
    __syncthreads();
    float bb = b1[c];
    for (int r = 0; r < 16; r++) {
        float acc = bb;
        #pragma unroll 4
        for (int hh = 0; hh < H; hh++)
            acc = fmaf(sx[r * H + hh], W1[hh * H + c],
                  fmaf(sy[r * H + hh], g_P[hh * H + c], acc));
        out[(size_t)BA * H + (i0 + r) * H + c] = fmaxf(acc, 0.0f);
    }
}

// ---------------------------------------------------------------------------
// Kernel 5: v_C = relu([vs0 | veC] @ W2 + b2)  -> out[0 ...]
// [2048,1664]@[1664,128]. grid 256 blocks, 128 threads, 8 rows/thread.
// ---------------------------------------------------------------------------
#define RB 8
__global__ void __launch_bounds__(128)
vC_kernel(const float* __restrict__ vs, const float* __restrict__ W2,
          const float* __restrict__ b2, float* __restrict__ out)
{
    __shared__ float sw[64 * H];    // 32 KB W2 tile
    __shared__ float sx[RB * 64];   // 2 KB  x tile
    const int c  = threadIdx.x;
    const int i0 = blockIdx.x * RB;

    float acc[RB];
    #pragma unroll
    for (int r = 0; r < RB; r++) acc[r] = 0.0f;

    for (int ch = 0; ch < 26; ch++) {
        const int j0 = ch * 64;
        // W2 tile: 64x128 floats, coalesced float4
        const float4* w4  = (const float4*)(W2 + (size_t)j0 * H);
        float4*       sw4 = (float4*)sw;
        #pragma unroll
        for (int t = 0; t < 16; t++) sw4[t * 128 + c] = w4[t * 128 + c];
        // x tile: RB rows x 64
        {
            int r = c >> 4, q = c & 15;
            const float* src = (j0 < 128)
                ? (vs + (size_t)(i0 + r) * H + j0 + q * 4)
                : (g_veC + (size_t)(i0 + r) * KF * H + (j0 - 128) + q * 4);
            ((float4*)sx)[c] = *(const float4*)src;
        }
        __syncthreads();
        #pragma unroll 4
        for (int jj = 0; jj < 64; jj++) {
            float wv = sw[jj * H + c];
            #pragma unroll
            for (int r = 0; r < RB; r++)
                acc[r] = fmaf(sx[r * 64 + jj], wv, acc[r]);
        }
        __syncthreads();
    }
    float bb = b2[c];
    #pragma unroll
    for (int r = 0; r < RB; r++)
        out[(size_t)(i0 + r) * H + c] = fmaxf(acc[r] + bb, 0.0f);
}

// ---------------------------------------------------------------------------
extern "C" void kernel_launch(void* const* d_in, const int* in_sizes, int n_in,
                              void* d_out, int out_size)
{
    const float* vs   = (const float*)d_in[0];
    const float* ve   = (const float*)d_in[1];
    const int*   dead = (const int*)  d_in[2];
    const float* Wq   = (const float*)d_in[3];
    const float* Wk   = (const float*)d_in[4];
    const float* Wv   = (const float*)d_in[5];
    const float* W1   = (const float*)d_in[6];
    const float* b1   = (const float*)d_in[7];
    const float* W2   = (const float*)d_in[8];
    const float* b2   = (const float*)d_in[9];
    float* out = (float*)d_out;

    prep_MP   <<<dim3(128, 2), 128>>>(Wq, Wk, Wv, W1);
    qk_kernel <<<128, 128>>>(vs);
    main_kernel<<<BA, 256>>>(ve, dead);
    vM_kernel <<<128, 128>>>(vs, W1, b1, out);
    vC_kernel <<<BA / RB, 128>>>(vs, W2, b2, out);
}

// round 4
// speedup vs baseline: 1.6918x; 1.6918x over previous
#include <cuda_runtime.h>
#include <math.h>

#define BA 2048          // B*A
#define E  256
#define H  128
#define KF 12
#define NORM 0.08838834764831845f   // 1/sqrt(128)

// Scratch (static __device__ to satisfy no-alloc rule)
__device__ float g_qk [BA * H];              // vs0 @ (Wq @ Wk^T)
__device__ float g_wve[BA * H];              // softmax-weighted sum of ve rows
__device__ float g_veC[(size_t)BA * KF * H]; // gathered top-12 entity rows
__device__ float g_M  [H * H];               // Wq @ Wk^T
__device__ float g_P  [H * H];               // Wv @ W1[H:,:]

// ---------------------------------------------------------------------------
// Kernel 1: tiny 128x128 weight products. grid (128, 2), 128 threads.
// ---------------------------------------------------------------------------
__global__ void prep_MP(const float* __restrict__ Wq, const float* __restrict__ Wk,
                        const float* __restrict__ Wv, const float* __restrict__ W1)
{
    __shared__ float arow[H];
    int r = blockIdx.x;
    int c = threadIdx.x;
    int m = blockIdx.y;
    const float* A = (m == 0) ? Wq : Wv;
    arow[c] = A[r * H + c];
    __syncthreads();

    float acc = 0.0f;
    if (m == 0) {
        const float4* wk4 = (const float4*)(Wk + c * H);
        #pragma unroll 8
        for (int d4 = 0; d4 < H / 4; d4++) {
            float4 w = wk4[d4];
            acc += arow[4 * d4 + 0] * w.x + arow[4 * d4 + 1] * w.y
                 + arow[4 * d4 + 2] * w.z + arow[4 * d4 + 3] * w.w;
        }
        g_M[r * H + c] = acc;
    } else {
        #pragma unroll 8
        for (int d = 0; d < H; d++)
            acc = fmaf(arow[d], W1[(H + d) * H + c], acc);
        g_P[r * H + c] = acc;
    }
}

// ---------------------------------------------------------------------------
// Kernel 2: qk = vs0 @ M   ([2048,128] @ [128,128]). grid 128, 128 threads.
// ---------------------------------------------------------------------------
__global__ void qk_kernel(const float* __restrict__ vs)
{
    __shared__ float Ms[H * H];
    __shared__ float xs[16 * H];
    int c  = threadIdx.x;
    int i0 = blockIdx.x * 16;
    for (int k = 0; k < H; k++) Ms[k * H + c] = g_M[k * H + c];
    for (int r = 0; r < 16; r++) xs[r * H + c] = vs[(i0 + r) * H + c];
    __syncthreads();
    for (int r = 0; r < 16; r++) {
        float acc = 0.0f;
        #pragma unroll 8
        for (int h = 0; h < H; h++)
            acc = fmaf(xs[r * H + h], Ms[h * H + c], acc);
        g_qk[(i0 + r) * H + c] = acc;
    }
}

// ---------------------------------------------------------------------------
// Kernel 3: MAIN. One CTA per (b,a), 256 threads, SINGLE pass over ve.
// Online softmax: each warp streams its 32 entities once, computing compat
// AND a running weighted accumulation (m, s, acc). Cross-warp combine in
// smem. Top-12 selected on compat (monotone in score, same tie-break).
// ---------------------------------------------------------------------------
__global__ void __launch_bounds__(256)
main_kernel(const float* __restrict__ ve, const int* __restrict__ dead)
{
    __shared__ float scomp[E];        // compat (with -inf dead mask)
    __shared__ float swm[8], sws[8];  // per-warp online max / sum
    __shared__ float sacc[8 * H];     // per-warp weighted accumulators
    __shared__ int   ssel[KF];

    const int i   = blockIdx.x;
    const int tid = threadIdx.x;
    const int w   = tid >> 5;
    const int l   = tid & 31;

    const float4* ve4 = (const float4*)(ve + (size_t)i * E * H);
    const float4  qk4 = ((const float4*)(g_qk + (size_t)i * H))[l];
    const int*    dr  = dead + i * E;

    float  m = -INFINITY, s = 0.0f;
    float4 acc = make_float4(0.f, 0.f, 0.f, 0.f);

    #pragma unroll 2
    for (int eo = 0; eo < 32; eo += 4) {
        const int e = w * 32 + eo;
        float4 r0 = ve4[(e + 0) * 32 + l];
        float4 r1 = ve4[(e + 1) * 32 + l];
        float4 r2 = ve4[(e + 2) * 32 + l];
        float4 r3 = ve4[(e + 3) * 32 + l];
        float s0 = r0.x * qk4.x + r0.y * qk4.y + r0.z * qk4.z + r0.w * qk4.w;
        float s1 = r1.x * qk4.x + r1.y * qk4.y + r1.z * qk4.z + r1.w * qk4.w;
        float s2 = r2.x * qk4.x + r2.y * qk4.y + r2.z * qk4.z + r2.w * qk4.w;
        float s3 = r3.x * qk4.x + r3.y * qk4.y + r3.z * qk4.z + r3.w * qk4.w;
        #pragma unroll
        for (int off = 16; off; off >>= 1) {
            s0 += __shfl_xor_sync(0xffffffffu, s0, off);
            s1 += __shfl_xor_sync(0xffffffffu, s1, off);
            s2 += __shfl_xor_sync(0xffffffffu, s2, off);
            s3 += __shfl_xor_sync(0xffffffffu, s3, off);
        }
        const float c0 = dr[e + 0] ? -INFINITY : NORM * s0;
        const float c1 = dr[e + 1] ? -INFINITY : NORM * s1;
        const float c2 = dr[e + 2] ? -INFINITY : NORM * s2;
        const float c3 = dr[e + 3] ? -INFINITY : NORM * s3;
        if (l < 4)
            scomp[e + l] = (l == 0) ? c0 : (l == 1) ? c1 : (l == 2) ? c2 : c3;

        float mn = fmaxf(fmaxf(fmaxf(c0, c1), fmaxf(c2, c3)), m);
        if (mn != -INFINITY) {
            float sc = __expf(m - mn);
            float p0 = __expf(c0 - mn);
            float p1 = __expf(c1 - mn);
            float p2 = __expf(c2 - mn);
            float p3 = __expf(c3 - mn);
            s = fmaf(s, sc, p0 + p1 + p2 + p3);
            acc.x = fmaf(acc.x, sc, p0 * r0.x + p1 * r1.x + p2 * r2.x + p3 * r3.x);
            acc.y = fmaf(acc.y, sc, p0 * r0.y + p1 * r1.y + p2 * r2.y + p3 * r3.y);
            acc.z = fmaf(acc.z, sc, p0 * r0.z + p1 * r1.z + p2 * r2.z + p3 * r3.z);
            acc.w = fmaf(acc.w, sc, p0 * r0.w + p1 * r1.w + p2 * r2.w + p3 * r3.w);
            m = mn;
        }
    }

    if (l == 0) { swm[w] = m; sws[w] = s; }
    ((float4*)sacc)[w * 32 + l] = acc;
    __syncthreads();

    // ---- cross-warp combine -> wve (threads 0..127) ----
    if (tid < H) {
        float M = swm[0];
        #pragma unroll
        for (int j = 1; j < 8; j++) M = fmaxf(M, swm[j]);
        float tot = 0.0f, sum = 0.0f;
        if (M != -INFINITY) {
            #pragma unroll
            for (int j = 0; j < 8; j++) {
                float f = __expf(swm[j] - M);
                tot = fmaf(sws[j], f, tot);
                sum = fmaf(f, sacc[j * H + tid], sum);
            }
        }
        g_wve[(size_t)i * H + tid] = (tot > 0.0f) ? sum / tot : 0.0f;
    }

    // ---- top-12 on compat (warp 0): desc value, asc index ties ----
    if (w == 0) {
        unsigned sel = 0;   // bit j: my entity j*32+l already selected
        for (int k = 0; k < KF; k++) {
            float bv = -INFINITY; int bi = 0x7fffffff;
            #pragma unroll
            for (int j = 0; j < 8; j++) {
                if ((sel >> j) & 1u) continue;
                int e = j * 32 + l;
                float v = scomp[e];
                if (v > bv || (v == bv && e < bi)) { bv = v; bi = e; }
            }
            #pragma unroll
            for (int off = 16; off; off >>= 1) {
                float ov = __shfl_xor_sync(0xffffffffu, bv, off);
                int   oi = __shfl_xor_sync(0xffffffffu, bi, off);
                if (ov > bv || (ov == bv && oi < bi)) { bv = ov; bi = oi; }
            }
            if ((bi & 31) == l) sel |= 1u << (bi >> 5);
            if (l == 0) ssel[k] = bi;
        }
    }
    __syncthreads();

    // ---- gather selected rows (8 warps, strided over 12) ----
    for (int k = w; k < KF; k += 8) {
        int e = ssel[k];
        ((float4*)g_veC)[((size_t)i * KF + k) * 32 + l] = ve4[e * 32 + l];
    }
}

// ---------------------------------------------------------------------------
// Kernel 4: v_M = relu([vs0|wve] @ [W1a;P] + b1). K=256 in 4 chunks of 64.
// grid 256, 128 threads, 8 rows/block. Same structure as vC.
// ---------------------------------------------------------------------------
#define RBM 8
__global__ void __launch_bounds__(128)
vM_kernel(const float* __restrict__ vs, const float* __restrict__ W1,
          const float* __restrict__ b1, float* __restrict__ out)
{
    __shared__ float sw[64 * H];    // 32 KB
    __shared__ float sx[RBM * 64];
    const int c  = threadIdx.x;
    const int i0 = blockIdx.x * RBM;

    float acc[RBM];
    #pragma unroll
    for (int r = 0; r < RBM; r++) acc[r] = 0.0f;

    #pragma unroll
    for (int ch = 0; ch < 4; ch++) {
        const int j0 = ch * 64;
        const float* wsrc = (j0 < 128) ? (W1 + (size_t)j0 * H)
                                       : (g_P + (size_t)(j0 - 128) * H);
        const float4* w4  = (const float4*)wsrc;
        float4*       sw4 = (float4*)sw;
        #pragma unroll
        for (int t = 0; t < 16; t++) sw4[t * 128 + c] = w4[t * 128 + c];
        {
            int r = c >> 4, q = c & 15;
            const float* src = (j0 < 128)
                ? (vs    + (size_t)(i0 + r) * H + j0 + q * 4)
                : (g_wve + (size_t)(i0 + r) * H + (j0 - 128) + q * 4);
            ((float4*)sx)[c] = *(const float4*)src;
        }
        __syncthreads();
        #pragma unroll 4
        for (int jj = 0; jj < 64; jj++) {
            float wv = sw[jj * H + c];
            #pragma unroll
            for (int r = 0; r < RBM; r++)
                acc[r] = fmaf(sx[r * 64 + jj], wv, acc[r]);
        }
        __syncthreads();
    }
    float bb = b1[c];
    #pragma unroll
    for (int r = 0; r < RBM; r++)
        out[(size_t)BA * H + (size_t)(i0 + r) * H + c] = fmaxf(acc[r] + bb, 0.0f);
}

// ---------------------------------------------------------------------------
// Kernel 5: v_C = relu([vs0 | veC] @ W2 + b2). [2048,1664]@[1664,128].
// 256 blocks x 256 threads, K split in two halves of 26 x 32-row chunks.
// ---------------------------------------------------------------------------
#define RBC 8
__global__ void __launch_bounds__(256)
vC_kernel(const float* __restrict__ vs, const float* __restrict__ W2,
          const float* __restrict__ b2, float* __restrict__ out)
{
    __shared__ float sw[2][32 * H];    // 32 KB
    __shared__ float sx[2][RBC * 32];  // 2 KB
    __shared__ float sred[RBC * H];    // 4 KB
    const int tid = threadIdx.x;
    const int hf  = tid >> 7;          // K-half
    const int c   = tid & 127;         // output column
    const int i0  = blockIdx.x * RBC;

    float acc[RBC];
    #pragma unroll
    for (int r = 0; r < RBC; r++) acc[r] = 0.0f;

    for (int ch = 0; ch < 26; ch++) {
        const int j0 = (hf * 26 + ch) * 32;   // global K offset
        // weight tile 32x128, 8 float4 per thread
        const float4* w4  = (const float4*)(W2 + (size_t)j0 * H);
        float4*       sw4 = (float4*)sw[hf];
        #pragma unroll
        for (int t = 0; t < 8; t++) sw4[t * 128 + c] = w4[t * 128 + c];
        // x tile 8x32 (threads c<64 of each half)
        if (c < 64) {
            int r = c >> 3, q = c & 7;
            const float* src = (j0 < 128)
                ? (vs    + (size_t)(i0 + r) * H + j0 + q * 4)
                : (g_veC + (size_t)(i0 + r) * KF * H + (j0 - 128) + q * 4);
            ((float4*)sx[hf])[c] = *(const float4*)src;
        }
        __syncthreads();
        #pragma unroll 4
        for (int jj = 0; jj < 32; jj++) {
            float wv = sw[hf][jj * H + c];
            #pragma unroll
            for (int r = 0; r < RBC; r++)
                acc[r] = fmaf(sx[hf][r * 32 + jj], wv, acc[r]);
        }
        __syncthreads();
    }
    if (hf) {
        #pragma unroll
        for (int r = 0; r < RBC; r++) sred[r * H + c] = acc[r];
    }
    __syncthreads();
    if (!hf) {
        float bb = b2[c];
        #pragma unroll
        for (int r = 0; r < RBC; r++)
            out[(size_t)(i0 + r) * H + c] =
                fmaxf(acc[r] + sred[r * H + c] + bb, 0.0f);
    }
}

// ---------------------------------------------------------------------------
extern "C" void kernel_launch(void* const* d_in, const int* in_sizes, int n_in,
                              void* d_out, int out_size)
{
    const float* vs   = (const float*)d_in[0];
    const float* ve   = (const float*)d_in[1];
    const int*   dead = (const int*)  d_in[2];
    const float* Wq   = (const float*)d_in[3];
    const float* Wk   = (const float*)d_in[4];
    const float* Wv   = (const float*)d_in[5];
    const float* W1   = (const float*)d_in[6];
    const float* b1   = (const float*)d_in[7];
    const float* W2   = (const float*)d_in[8];
    const float* b2   = (const float*)d_in[9];
    float* out = (float*)d_out;

    prep_MP   <<<dim3(128, 2), 128>>>(Wq, Wk, Wv, W1);
    qk_kernel <<<128, 128>>>(vs);
    main_kernel<<<BA, 256>>>(ve, dead);
    vM_kernel <<<BA / RBM, 128>>>(vs, W1, b1, out);
    vC_kernel <<<BA / RBC, 256>>>(vs, W2, b2, out);
}